// round 3
// baseline (speedup 1.0000x reference)
#include <cuda_runtime.h>

// Problem constants (from reference)
#define N_NODES 50000
#define N_EDGES 1600000
#define E_TOT   (N_EDGES + N_NODES)
#define FDIM    128
#define NHEAD   2
#define CDIM    64
#define NEG_SLOPE 0.2f

#define SCAN_BLK 1024
#define SCAN_NBLK ((N_NODES + SCAN_BLK - 1) / SCAN_BLK)   // 49

// ---------------- device scratch (no runtime allocation) ----------------
__device__ int g_is64;
__device__ int g_src[N_EDGES];
__device__ int g_dst[N_EDGES];
__device__ int g_counts[N_NODES];
__device__ int g_rowptr[N_NODES + 1];
__device__ int g_fill[N_NODES];
__device__ int g_col[E_TOT];
__device__ int g_partials[64];
__device__ __align__(16) float g_h[(size_t)N_NODES * FDIM];
__device__ __align__(16) float g_x[(size_t)N_NODES * FDIM];
__device__ __align__(16) float g_esrc[N_NODES * NHEAD];
__device__ __align__(16) float g_edst[N_NODES * NHEAD];

// ---------------- edge_index dtype probe + conversion ----------------
// int64 indices: every 8-byte word is a value in [0, N). If the buffer is
// actually int32, interpreting pairs as int64 yields lo + (hi<<32) with hi
// almost surely nonzero -> >= N. Check 16 words.
__global__ void k_detect(const long long* ei) {
    if (blockIdx.x == 0 && threadIdx.x == 0) {
        int ok = 1;
        for (int i = 0; i < 16; i++) {
            long long v = ei[i];
            if (v < 0 || v >= (long long)N_NODES) { ok = 0; break; }
        }
        g_is64 = ok;
    }
}

__global__ void k_convert(const void* eiv) {
    int e = blockIdx.x * blockDim.x + threadIdx.x;
    if (e >= N_EDGES) return;
    if (g_is64) {
        const long long* p = (const long long*)eiv;
        g_src[e] = (int)p[e];
        g_dst[e] = (int)p[N_EDGES + e];
    } else {
        const int* p = (const int*)eiv;
        g_src[e] = p[e];
        g_dst[e] = p[N_EDGES + e];
    }
}

// ---------------- CSR build (by dst), self-loop reserved at slot 0 ----------------
__global__ void k_init_counts() {
    int i = blockIdx.x * blockDim.x + threadIdx.x;
    if (i < N_NODES) g_counts[i] = 1;   // self loop
}

__global__ void k_hist() {
    int e = blockIdx.x * blockDim.x + threadIdx.x;
    if (e < N_EDGES) atomicAdd(&g_counts[g_dst[e]], 1);
}

__global__ void k_scan1() {
    __shared__ int sh[SCAN_BLK];
    int i = blockIdx.x * SCAN_BLK + threadIdx.x;
    int v = (i < N_NODES) ? g_counts[i] : 0;
    sh[threadIdx.x] = v;
    __syncthreads();
    for (int o = 1; o < SCAN_BLK; o <<= 1) {
        int t = 0;
        if ((int)threadIdx.x >= o) t = sh[threadIdx.x - o];
        __syncthreads();
        sh[threadIdx.x] += t;
        __syncthreads();
    }
    if (i < N_NODES) g_rowptr[i] = sh[threadIdx.x] - v;   // block-local exclusive
    if (threadIdx.x == SCAN_BLK - 1) g_partials[blockIdx.x] = sh[SCAN_BLK - 1];
}

__global__ void k_scan2() {
    __shared__ int sh[64];
    int v = ((int)threadIdx.x < SCAN_NBLK) ? g_partials[threadIdx.x] : 0;
    sh[threadIdx.x] = v;
    __syncthreads();
    for (int o = 1; o < 64; o <<= 1) {
        int t = 0;
        if ((int)threadIdx.x >= o) t = sh[threadIdx.x - o];
        __syncthreads();
        sh[threadIdx.x] += t;
        __syncthreads();
    }
    if ((int)threadIdx.x < SCAN_NBLK) g_partials[threadIdx.x] = sh[threadIdx.x] - v;  // exclusive
}

__global__ void k_scan3() {
    int i = blockIdx.x * SCAN_BLK + threadIdx.x;
    if (i < N_NODES) g_rowptr[i] += g_partials[blockIdx.x];
    if (i == 0) g_rowptr[N_NODES] = E_TOT;
}

__global__ void k_selfloop() {
    int n = blockIdx.x * blockDim.x + threadIdx.x;
    if (n < N_NODES) {
        g_col[g_rowptr[n]] = n;
        g_fill[n] = 1;
    }
}

__global__ void k_scatter() {
    int e = blockIdx.x * blockDim.x + threadIdx.x;
    if (e >= N_EDGES) return;
    int d = g_dst[e];
    int pos = g_rowptr[d] + atomicAdd(&g_fill[d], 1);
    g_col[pos] = g_src[e];
}

// ---------------- SGEMM: C[M,128] = A[M,128] @ B[128,128] ----------------
// BM=128, BN=128, BK=8, 256 threads, 8x8 microtile per thread.
__global__ __launch_bounds__(256) void k_sgemm(const float* __restrict__ A,
                                               const float* __restrict__ B,
                                               float* __restrict__ C, int M) {
    __shared__ float As[8][128];   // transposed: As[k][m]
    __shared__ float Bs[8][128];

    const int tid  = threadIdx.x;
    const int row0 = blockIdx.x * 128;
    const int tr   = tid >> 4;     // 0..15
    const int tc   = tid & 15;     // 0..15

    const int laRow = tid >> 1;          // 0..127
    const int laCol = (tid & 1) * 4;     // 0 or 4
    const int lbRow = tid >> 5;          // 0..7
    const int lbCol = (tid & 31) * 4;    // 0..124

    float acc[8][8];
#pragma unroll
    for (int i = 0; i < 8; i++)
#pragma unroll
        for (int j = 0; j < 8; j++) acc[i][j] = 0.f;

    for (int k0 = 0; k0 < 128; k0 += 8) {
        float4 av = make_float4(0.f, 0.f, 0.f, 0.f);
        int arow = row0 + laRow;
        if (arow < M) av = *(const float4*)&A[(size_t)arow * 128 + k0 + laCol];
        As[laCol + 0][laRow] = av.x;
        As[laCol + 1][laRow] = av.y;
        As[laCol + 2][laRow] = av.z;
        As[laCol + 3][laRow] = av.w;

        float4 bv = *(const float4*)&B[(k0 + lbRow) * 128 + lbCol];
        *(float4*)&Bs[lbRow][lbCol] = bv;
        __syncthreads();

#pragma unroll
        for (int k = 0; k < 8; k++) {
            float ra[8], rb[8];
#pragma unroll
            for (int i = 0; i < 8; i++) ra[i] = As[k][tr * 8 + i];
#pragma unroll
            for (int j = 0; j < 8; j++) rb[j] = Bs[k][tc * 8 + j];
#pragma unroll
            for (int i = 0; i < 8; i++)
#pragma unroll
                for (int j = 0; j < 8; j++) acc[i][j] += ra[i] * rb[j];
        }
        __syncthreads();
    }

#pragma unroll
    for (int i = 0; i < 8; i++) {
        int row = row0 + tr * 8 + i;
        if (row < M) {
            float4 v0 = make_float4(acc[i][0], acc[i][1], acc[i][2], acc[i][3]);
            float4 v1 = make_float4(acc[i][4], acc[i][5], acc[i][6], acc[i][7]);
            *(float4*)&C[(size_t)row * 128 + tc * 8]     = v0;
            *(float4*)&C[(size_t)row * 128 + tc * 8 + 4] = v1;
        }
    }
}

// ---------------- attention logit dots: e_src/e_dst [N, H] ----------------
__global__ void k_edot(const float* __restrict__ h,
                       const float* __restrict__ a_src,
                       const float* __restrict__ a_dst) {
    int warp = (blockIdx.x * blockDim.x + threadIdx.x) >> 5;
    int lane = threadIdx.x & 31;
    if (warp >= N_NODES) return;

    float4 hv = *(const float4*)&h[(size_t)warp * 128 + lane * 4];
    int head = lane >> 4;
    int off  = head * 64 + (lane & 15) * 4;
    float4 as = *(const float4*)&a_src[off];
    float4 ad = *(const float4*)&a_dst[off];

    float ds = hv.x * as.x + hv.y * as.y + hv.z * as.z + hv.w * as.w;
    float dd = hv.x * ad.x + hv.y * ad.y + hv.z * ad.z + hv.w * ad.w;
#pragma unroll
    for (int o = 8; o > 0; o >>= 1) {
        ds += __shfl_down_sync(0xffffffffu, ds, o, 16);
        dd += __shfl_down_sync(0xffffffffu, dd, o, 16);
    }
    if ((lane & 15) == 0) {
        g_esrc[warp * 2 + head] = ds;
        g_edst[warp * 2 + head] = dd;
    }
}

// ---------------- edge aggregation: one warp per dst, online softmax ----------------
__global__ __launch_bounds__(256) void k_agg(const float* __restrict__ h,
                                             const float* __restrict__ bias,
                                             float* __restrict__ out, int do_relu) {
    int warp = (blockIdx.x * blockDim.x + threadIdx.x) >> 5;
    int lane = threadIdx.x & 31;
    if (warp >= N_NODES) return;

    const int d    = warp;
    const int head = lane >> 4;
    const float ed = g_edst[d * 2 + head];
    const int beg  = g_rowptr[d];
    const int end  = g_rowptr[d + 1];

    float m = -1e30f, s = 0.f;
    float4 acc = make_float4(0.f, 0.f, 0.f, 0.f);
    const float4* h4 = (const float4*)h;

    for (int e = beg; e < end; e++) {
        int src  = g_col[e];
        float es = g_esrc[src * 2 + head];
        float xx = es + ed;
        float lv = xx > 0.f ? xx : NEG_SLOPE * xx;
        float nm = fmaxf(m, lv);
        float scale = __expf(m - nm);
        float p     = __expf(lv - nm);
        float4 hv = h4[(size_t)src * 32 + lane];
        s     = s * scale + p;
        acc.x = acc.x * scale + p * hv.x;
        acc.y = acc.y * scale + p * hv.y;
        acc.z = acc.z * scale + p * hv.z;
        acc.w = acc.w * scale + p * hv.w;
        m = nm;
    }

    float inv = 1.f / (s + 1e-16f);
    float4 bv = ((const float4*)bias)[lane];
    float4 o;
    o.x = acc.x * inv + bv.x;
    o.y = acc.y * inv + bv.y;
    o.z = acc.z * inv + bv.z;
    o.w = acc.w * inv + bv.w;
    if (do_relu) {
        o.x = fmaxf(o.x, 0.f); o.y = fmaxf(o.y, 0.f);
        o.z = fmaxf(o.z, 0.f); o.w = fmaxf(o.w, 0.f);
    }
    ((float4*)out)[(size_t)d * 32 + lane] = o;
}

// ---------------- host side ----------------
static void run_layer(const float* xin, const float* W, const float* a_src,
                      const float* a_dst, const float* b, float* h_buf,
                      float* out_buf, int do_relu) {
    const int gemm_blocks = (N_NODES + 127) / 128;
    k_sgemm<<<gemm_blocks, 256>>>(xin, W, h_buf, N_NODES);
    const int warp_blocks = (N_NODES * 32 + 255) / 256;
    k_edot<<<warp_blocks, 256>>>(h_buf, a_src, a_dst);
    k_agg<<<warp_blocks, 256>>>(h_buf, b, out_buf, do_relu);
}

extern "C" void kernel_launch(void* const* d_in, const int* in_sizes, int n_in,
                              void* d_out, int out_size) {
    const float* x      = (const float*)d_in[0];
    const void*  ei     = d_in[1];
    const float* W_in   = (const float*)d_in[2];
    const float* as_in  = (const float*)d_in[3];
    const float* ad_in  = (const float*)d_in[4];
    const float* b_in   = (const float*)d_in[5];
    const float* W_h    = (const float*)d_in[6];
    const float* as_h   = (const float*)d_in[7];
    const float* ad_h   = (const float*)d_in[8];
    const float* b_h    = (const float*)d_in[9];
    const float* W_out  = (const float*)d_in[10];
    const float* as_out = (const float*)d_in[11];
    const float* ad_out = (const float*)d_in[12];
    const float* b_out  = (const float*)d_in[13];
    float* out = (float*)d_out;

    float *p_h = nullptr, *p_x = nullptr;
    cudaGetSymbolAddress((void**)&p_h, g_h);
    cudaGetSymbolAddress((void**)&p_x, g_x);

    // ---- CSR build (recomputed every replay; deterministic) ----
    const int eb = (N_EDGES + 255) / 256;
    const int nb = (N_NODES + 255) / 256;
    k_detect<<<1, 32>>>((const long long*)ei);
    k_convert<<<eb, 256>>>(ei);
    k_init_counts<<<nb, 256>>>();
    k_hist<<<eb, 256>>>();
    k_scan1<<<SCAN_NBLK, SCAN_BLK>>>();
    k_scan2<<<1, 64>>>();
    k_scan3<<<SCAN_NBLK, SCAN_BLK>>>();
    k_selfloop<<<nb, 256>>>();
    k_scatter<<<eb, 256>>>();

    // ---- 4 GAT layers ----
    run_layer(x,   W_in,              as_in,        ad_in,        b_in,        p_h, p_x, 1);
    run_layer(p_x, W_h,               as_h,         ad_h,         b_h,         p_h, p_x, 1);
    run_layer(p_x, W_h + 128 * 128,   as_h + 128,   ad_h + 128,   b_h + 128,   p_h, p_x, 1);
    run_layer(p_x, W_out,             as_out,       ad_out,       b_out,       p_h, out, 0);
}

// round 5
// speedup vs baseline: 1.0588x; 1.0588x over previous
#include <cuda_runtime.h>

// Problem constants
#define N_NODES 50000
#define N_EDGES 1600000
#define E_TOT   (N_EDGES + N_NODES)
#define FDIM    128
#define NHEAD   2
#define NEG_SLOPE 0.2f

#define SCAN_BLK 1024
#define SCAN_NBLK ((N_NODES + SCAN_BLK - 1) / SCAN_BLK)   // 49

// ---------------- device scratch ----------------
__device__ int g_is64;
__device__ int g_src[N_EDGES];
__device__ int g_dst[N_EDGES];
__device__ int g_counts[N_NODES];
__device__ int g_rowptr[N_NODES + 1];
__device__ int g_fill[N_NODES];
__device__ int g_col[E_TOT];
__device__ int g_partials[64];
__device__ __align__(16) float g_h[(size_t)N_NODES * FDIM];
__device__ __align__(16) float g_x[(size_t)N_NODES * FDIM];
__device__ __align__(16) float g_esrc[N_NODES * NHEAD];
__device__ __align__(16) float g_edst[N_NODES * NHEAD];

// ---------------- packed f32x2 helpers ----------------
#define FMA2(d, a, b, c) \
    asm("fma.rn.f32x2 %0, %1, %2, %3;" : "=l"(d) : "l"(a), "l"(b), "l"(c))
#define PACK2(d, x) \
    asm("mov.b64 %0, {%1, %1};" : "=l"(d) : "r"(__float_as_uint(x)))
#define UNPACK2(lo, hi, v) \
    do { unsigned _l, _h; \
         asm("mov.b64 {%0, %1}, %2;" : "=r"(_l), "=r"(_h) : "l"(v)); \
         lo = __uint_as_float(_l); hi = __uint_as_float(_h); } while (0)

// ---------------- CSR build ----------------
// init counts to 1 (self loop) + dtype probe
__global__ void k_init_detect(const long long* ei) {
    int i = blockIdx.x * blockDim.x + threadIdx.x;
    if (i < N_NODES) g_counts[i] = 1;
    if (i == 0) {
        int ok = 1;
        for (int t = 0; t < 16; t++) {
            long long v = ei[t];
            if (v < 0 || v >= (long long)N_NODES) { ok = 0; break; }
        }
        g_is64 = ok;
    }
}

// convert edge_index to int32 + histogram by dst, fused
__global__ void k_convert_hist(const void* eiv) {
    int e = blockIdx.x * blockDim.x + threadIdx.x;
    if (e >= N_EDGES) return;
    int s, d;
    if (g_is64) {
        const long long* p = (const long long*)eiv;
        s = (int)p[e];
        d = (int)p[N_EDGES + e];
    } else {
        const int* p = (const int*)eiv;
        s = p[e];
        d = p[N_EDGES + e];
    }
    g_src[e] = s;
    g_dst[e] = d;
    atomicAdd(&g_counts[d], 1);
}

__global__ void k_scan1() {
    __shared__ int sh[SCAN_BLK];
    int i = blockIdx.x * SCAN_BLK + threadIdx.x;
    int v = (i < N_NODES) ? g_counts[i] : 0;
    sh[threadIdx.x] = v;
    __syncthreads();
    for (int o = 1; o < SCAN_BLK; o <<= 1) {
        int t = 0;
        if ((int)threadIdx.x >= o) t = sh[threadIdx.x - o];
        __syncthreads();
        sh[threadIdx.x] += t;
        __syncthreads();
    }
    if (i < N_NODES) g_rowptr[i] = sh[threadIdx.x] - v;
    if (threadIdx.x == SCAN_BLK - 1) g_partials[blockIdx.x] = sh[SCAN_BLK - 1];
}

__global__ void k_scan2() {
    __shared__ int sh[64];
    int v = ((int)threadIdx.x < SCAN_NBLK) ? g_partials[threadIdx.x] : 0;
    sh[threadIdx.x] = v;
    __syncthreads();
    for (int o = 1; o < 64; o <<= 1) {
        int t = 0;
        if ((int)threadIdx.x >= o) t = sh[threadIdx.x - o];
        __syncthreads();
        sh[threadIdx.x] += t;
        __syncthreads();
    }
    if ((int)threadIdx.x < SCAN_NBLK) g_partials[threadIdx.x] = sh[threadIdx.x] - v;
}

// add block offsets + write self-loop in slot 0 (fused)
__global__ void k_scan3_selfloop() {
    int i = blockIdx.x * SCAN_BLK + threadIdx.x;
    if (i < N_NODES) {
        int rp = g_rowptr[i] + g_partials[blockIdx.x];
        g_rowptr[i] = rp;
        g_col[rp] = i;      // self loop
        g_fill[i] = 1;
    }
    if (i == 0) g_rowptr[N_NODES] = E_TOT;
}

__global__ void k_scatter() {
    int e = blockIdx.x * blockDim.x + threadIdx.x;
    if (e >= N_EDGES) return;
    int d = g_dst[e];
    int pos = g_rowptr[d] + atomicAdd(&g_fill[d], 1);
    g_col[pos] = g_src[e];
}

// ---------------- SGEMM (f32x2 packed) + fused attention-logit epilogue ----
// C[M,128] = A[M,128] @ B[128,128]; also writes g_esrc/g_edst = C·a_src, C·a_dst
// BM=128, BN=128, BK=8, 256 threads, 8x8 microtile (packed as 8x4 f32x2).
__global__ __launch_bounds__(256, 2) void k_sgemm_fused(
    const float* __restrict__ A, const float* __restrict__ B,
    float* __restrict__ C,
    const float* __restrict__ a_src, const float* __restrict__ a_dst, int M) {
    __shared__ float As[8][128];   // transposed: As[k][m]
    __shared__ float Bs[8][128];

    const int tid  = threadIdx.x;
    const int row0 = blockIdx.x * 128;
    const int tr   = tid >> 4;     // 0..15
    const int tc   = tid & 15;     // 0..15

    const int laRow = tid >> 1;
    const int laCol = (tid & 1) * 4;
    const int lbRow = tid >> 5;
    const int lbCol = (tid & 31) * 4;

    unsigned long long acc[8][4];
#pragma unroll
    for (int i = 0; i < 8; i++)
#pragma unroll
        for (int p = 0; p < 4; p++) acc[i][p] = 0ull;

    for (int k0 = 0; k0 < 128; k0 += 8) {
        float4 av = make_float4(0.f, 0.f, 0.f, 0.f);
        int arow = row0 + laRow;
        if (arow < M) av = *(const float4*)&A[(size_t)arow * 128 + k0 + laCol];
        As[laCol + 0][laRow] = av.x;
        As[laCol + 1][laRow] = av.y;
        As[laCol + 2][laRow] = av.z;
        As[laCol + 3][laRow] = av.w;

        *(float4*)&Bs[lbRow][lbCol] = *(const float4*)&B[(k0 + lbRow) * 128 + lbCol];
        __syncthreads();

#pragma unroll
        for (int k = 0; k < 8; k++) {
            float4 a0 = *(const float4*)&As[k][tr * 8];
            float4 a1 = *(const float4*)&As[k][tr * 8 + 4];
            ulonglong2 rb0 = *(const ulonglong2*)&Bs[k][tc * 8];       // cols (0,1),(2,3)
            ulonglong2 rb1 = *(const ulonglong2*)&Bs[k][tc * 8 + 4];   // cols (4,5),(6,7)
            float avv[8] = {a0.x, a0.y, a0.z, a0.w, a1.x, a1.y, a1.z, a1.w};
#pragma unroll
            for (int i = 0; i < 8; i++) {
                unsigned long long ra;
                PACK2(ra, avv[i]);
                FMA2(acc[i][0], ra, rb0.x, acc[i][0]);
                FMA2(acc[i][1], ra, rb0.y, acc[i][1]);
                FMA2(acc[i][2], ra, rb1.x, acc[i][2]);
                FMA2(acc[i][3], ra, rb1.y, acc[i][3]);
            }
        }
        __syncthreads();
    }

    // ---- epilogue: store C + fused e_src/e_dst dot products ----
    // a_src/a_dst flattened [H*C]=128 matches column order of C exactly.
    float4 as0 = *(const float4*)&a_src[tc * 8];
    float4 as1 = *(const float4*)&a_src[tc * 8 + 4];
    float4 ad0 = *(const float4*)&a_dst[tc * 8];
    float4 ad1 = *(const float4*)&a_dst[tc * 8 + 4];

#pragma unroll
    for (int i = 0; i < 8; i++) {
        float c0, c1, c2, c3, c4, c5, c6, c7;
        UNPACK2(c0, c1, acc[i][0]);
        UNPACK2(c2, c3, acc[i][1]);
        UNPACK2(c4, c5, acc[i][2]);
        UNPACK2(c6, c7, acc[i][3]);

        int row = row0 + tr * 8 + i;
        if (row < M) {
            *(float4*)&C[(size_t)row * 128 + tc * 8]     = make_float4(c0, c1, c2, c3);
            *(float4*)&C[(size_t)row * 128 + tc * 8 + 4] = make_float4(c4, c5, c6, c7);
        }

        float ds = c0 * as0.x + c1 * as0.y + c2 * as0.z + c3 * as0.w
                 + c4 * as1.x + c5 * as1.y + c6 * as1.z + c7 * as1.w;
        float dd = c0 * ad0.x + c1 * ad0.y + c2 * ad0.z + c3 * ad0.w
                 + c4 * ad1.x + c5 * ad1.y + c6 * ad1.z + c7 * ad1.w;
#pragma unroll
        for (int o = 4; o > 0; o >>= 1) {
            ds += __shfl_down_sync(0xffffffffu, ds, o, 8);
            dd += __shfl_down_sync(0xffffffffu, dd, o, 8);
        }
        if (row < M && (tc & 7) == 0) {
            int head = tc >> 3;
            g_esrc[row * 2 + head] = ds;
            g_edst[row * 2 + head] = dd;
        }
    }
}

// ---------------- edge aggregation: one warp per dst, online softmax ------
__global__ __launch_bounds__(256) void k_agg(const float* __restrict__ h,
                                             const float* __restrict__ bias,
                                             float* __restrict__ out, int do_relu) {
    int warp = (blockIdx.x * blockDim.x + threadIdx.x) >> 5;
    int lane = threadIdx.x & 31;
    if (warp >= N_NODES) return;

    const int d    = warp;
    const int head = lane >> 4;
    const float ed = g_edst[d * 2 + head];
    const int beg  = g_rowptr[d];
    const int end  = g_rowptr[d + 1];

    float m = -1e30f, s = 0.f;
    float4 acc = make_float4(0.f, 0.f, 0.f, 0.f);
    const float4* h4 = (const float4*)h;

    int src = g_col[beg];
    for (int e = beg; e < end; e++) {
        int cur = src;
        if (e + 1 < end) src = g_col[e + 1];          // prefetch next index
        float es = g_esrc[cur * 2 + head];
        float4 hv = h4[(size_t)cur * 32 + lane];
        float xx = es + ed;
        float lv = xx > 0.f ? xx : NEG_SLOPE * xx;
        float nm = fmaxf(m, lv);
        float scale = __expf(m - nm);
        float p     = __expf(lv - nm);
        s     = s * scale + p;
        acc.x = acc.x * scale + p * hv.x;
        acc.y = acc.y * scale + p * hv.y;
        acc.z = acc.z * scale + p * hv.z;
        acc.w = acc.w * scale + p * hv.w;
        m = nm;
    }

    float inv = 1.f / (s + 1e-16f);
    float4 bv = ((const float4*)bias)[lane];
    float4 o;
    o.x = acc.x * inv + bv.x;
    o.y = acc.y * inv + bv.y;
    o.z = acc.z * inv + bv.z;
    o.w = acc.w * inv + bv.w;
    if (do_relu) {
        o.x = fmaxf(o.x, 0.f); o.y = fmaxf(o.y, 0.f);
        o.z = fmaxf(o.z, 0.f); o.w = fmaxf(o.w, 0.f);
    }
    ((float4*)out)[(size_t)d * 32 + lane] = o;
}

// ---------------- host side ----------------
static void run_layer(const float* xin, const float* W, const float* a_src,
                      const float* a_dst, const float* b, float* h_buf,
                      float* out_buf, int do_relu) {
    const int gemm_blocks = (N_NODES + 127) / 128;
    k_sgemm_fused<<<gemm_blocks, 256>>>(xin, W, h_buf, a_src, a_dst, N_NODES);
    const int warp_blocks = (N_NODES * 32 + 255) / 256;
    k_agg<<<warp_blocks, 256>>>(h_buf, b, out_buf, do_relu);
}

extern "C" void kernel_launch(void* const* d_in, const int* in_sizes, int n_in,
                              void* d_out, int out_size) {
    const float* x      = (const float*)d_in[0];
    const void*  ei     = d_in[1];
    const float* W_in   = (const float*)d_in[2];
    const float* as_in  = (const float*)d_in[3];
    const float* ad_in  = (const float*)d_in[4];
    const float* b_in   = (const float*)d_in[5];
    const float* W_h    = (const float*)d_in[6];
    const float* as_h   = (const float*)d_in[7];
    const float* ad_h   = (const float*)d_in[8];
    const float* b_h    = (const float*)d_in[9];
    const float* W_out  = (const float*)d_in[10];
    const float* as_out = (const float*)d_in[11];
    const float* ad_out = (const float*)d_in[12];
    const float* b_out  = (const float*)d_in[13];
    float* out = (float*)d_out;

    float *p_h = nullptr, *p_x = nullptr;
    cudaGetSymbolAddress((void**)&p_h, g_h);
    cudaGetSymbolAddress((void**)&p_x, g_x);

    // ---- CSR build (deterministic, recomputed each replay) ----
    const int eb = (N_EDGES + 255) / 256;
    const int nb = (N_NODES + 255) / 256;
    k_init_detect<<<nb, 256>>>((const long long*)ei);
    k_convert_hist<<<eb, 256>>>(ei);
    k_scan1<<<SCAN_NBLK, SCAN_BLK>>>();
    k_scan2<<<1, 64>>>();
    k_scan3_selfloop<<<SCAN_NBLK, SCAN_BLK>>>();
    k_scatter<<<eb, 256>>>();

    // ---- 4 GAT layers ----
    run_layer(x,   W_in,            as_in,      ad_in,      b_in,      p_h, p_x, 1);
    run_layer(p_x, W_h,             as_h,       ad_h,       b_h,       p_h, p_x, 1);
    run_layer(p_x, W_h + 128 * 128, as_h + 128, ad_h + 128, b_h + 128, p_h, p_x, 1);
    run_layer(p_x, W_out,           as_out,     ad_out,     b_out,     p_h, out, 0);
}

// round 6
// speedup vs baseline: 1.1330x; 1.0701x over previous
#include <cuda_runtime.h>
#include <cuda_fp16.h>

// Problem constants
#define N_NODES 50000
#define N_EDGES 1600000
#define E_TOT   (N_EDGES + N_NODES)
#define FDIM    128
#define NHEAD   2
#define NEG_SLOPE 0.2f

#define SCAN_BLK 1024
#define SCAN_NBLK ((N_NODES + SCAN_BLK - 1) / SCAN_BLK)   // 49

// ---------------- device scratch ----------------
__device__ int g_is64;
__device__ int g_src[N_EDGES];
__device__ int g_dst[N_EDGES];
__device__ int g_counts[N_NODES];
__device__ int g_rowptr[N_NODES + 1];
__device__ int g_fill[N_NODES];
__device__ int g_col[E_TOT];
__device__ int g_partials[64];
__device__ __align__(16) __half g_h16[(size_t)N_NODES * FDIM];   // fp16 features for gather
__device__ __align__(16) float  g_x[(size_t)N_NODES * FDIM];     // fp32 layer output
__device__ __align__(16) float  g_esrc[N_NODES * NHEAD];
__device__ __align__(16) float  g_edst[N_NODES * NHEAD];

// ---------------- packed f32x2 helpers ----------------
#define FMA2(d, a, b, c) \
    asm("fma.rn.f32x2 %0, %1, %2, %3;" : "=l"(d) : "l"(a), "l"(b), "l"(c))
#define PACK2(d, x) \
    asm("mov.b64 %0, {%1, %1};" : "=l"(d) : "r"(__float_as_uint(x)))
#define UNPACK2(lo, hi, v) \
    do { unsigned _l, _h; \
         asm("mov.b64 {%0, %1}, %2;" : "=r"(_l), "=r"(_h) : "l"(v)); \
         lo = __uint_as_float(_l); hi = __uint_as_float(_h); } while (0)

// ---------------- CSR build ----------------
__global__ void k_init_detect(const long long* ei) {
    int i = blockIdx.x * blockDim.x + threadIdx.x;
    if (i < N_NODES) g_counts[i] = 1;   // self loop
    if (i == 0) {
        int ok = 1;
        for (int t = 0; t < 16; t++) {
            long long v = ei[t];
            if (v < 0 || v >= (long long)N_NODES) { ok = 0; break; }
        }
        g_is64 = ok;
    }
}

__global__ void k_convert_hist(const void* eiv) {
    int e = blockIdx.x * blockDim.x + threadIdx.x;
    if (e >= N_EDGES) return;
    int s, d;
    if (g_is64) {
        const long long* p = (const long long*)eiv;
        s = (int)p[e];
        d = (int)p[N_EDGES + e];
    } else {
        const int* p = (const int*)eiv;
        s = p[e];
        d = p[N_EDGES + e];
    }
    g_src[e] = s;
    g_dst[e] = d;
    atomicAdd(&g_counts[d], 1);
}

__global__ void k_scan1() {
    __shared__ int sh[SCAN_BLK];
    int i = blockIdx.x * SCAN_BLK + threadIdx.x;
    int v = (i < N_NODES) ? g_counts[i] : 0;
    sh[threadIdx.x] = v;
    __syncthreads();
    for (int o = 1; o < SCAN_BLK; o <<= 1) {
        int t = 0;
        if ((int)threadIdx.x >= o) t = sh[threadIdx.x - o];
        __syncthreads();
        sh[threadIdx.x] += t;
        __syncthreads();
    }
    if (i < N_NODES) g_rowptr[i] = sh[threadIdx.x] - v;   // block-local exclusive
    if (threadIdx.x == SCAN_BLK - 1) g_partials[blockIdx.x] = sh[SCAN_BLK - 1];
}

// add block offsets (each block re-scans the 49 partials locally) + self loop
__global__ void k_scan3_selfloop() {
    __shared__ int sh[64];
    if (threadIdx.x < 64)
        sh[threadIdx.x] = ((int)threadIdx.x < SCAN_NBLK) ? g_partials[threadIdx.x] : 0;
    __syncthreads();
    for (int o = 1; o < 64; o <<= 1) {
        int t = 0;
        if (threadIdx.x < 64 && (int)threadIdx.x >= o) t = sh[threadIdx.x - o];
        __syncthreads();
        if (threadIdx.x < 64) sh[threadIdx.x] += t;
        __syncthreads();
    }
    int blockOff = (blockIdx.x == 0) ? 0 : sh[blockIdx.x - 1];  // exclusive
    int i = blockIdx.x * SCAN_BLK + threadIdx.x;
    if (i < N_NODES) {
        int rp = g_rowptr[i] + blockOff;
        g_rowptr[i] = rp;
        g_col[rp] = i;      // self loop in slot 0
        g_fill[i] = 1;
    }
    if (i == 0) g_rowptr[N_NODES] = E_TOT;
}

__global__ void k_scatter() {
    int e = blockIdx.x * blockDim.x + threadIdx.x;
    if (e >= N_EDGES) return;
    int d = g_dst[e];
    int pos = g_rowptr[d] + atomicAdd(&g_fill[d], 1);
    g_col[pos] = g_src[e];
}

// ---------------- SGEMM (f32x2) + fused logits, fp16 output ----------------
// h16[M,128] = fp16(A[M,128] @ B[128,128]); e_src/e_dst from fp32 accumulators.
__global__ __launch_bounds__(256, 2) void k_sgemm_fused(
    const float* __restrict__ A, const float* __restrict__ B,
    __half* __restrict__ C16,
    const float* __restrict__ a_src, const float* __restrict__ a_dst, int M) {
    __shared__ float As[8][128];   // transposed: As[k][m]
    __shared__ float Bs[8][128];

    const int tid  = threadIdx.x;
    const int row0 = blockIdx.x * 128;
    const int tr   = tid >> 4;
    const int tc   = tid & 15;

    const int laRow = tid >> 1;
    const int laCol = (tid & 1) * 4;
    const int lbRow = tid >> 5;
    const int lbCol = (tid & 31) * 4;

    unsigned long long acc[8][4];
#pragma unroll
    for (int i = 0; i < 8; i++)
#pragma unroll
        for (int p = 0; p < 4; p++) acc[i][p] = 0ull;

    for (int k0 = 0; k0 < 128; k0 += 8) {
        float4 av = make_float4(0.f, 0.f, 0.f, 0.f);
        int arow = row0 + laRow;
        if (arow < M) av = *(const float4*)&A[(size_t)arow * 128 + k0 + laCol];
        As[laCol + 0][laRow] = av.x;
        As[laCol + 1][laRow] = av.y;
        As[laCol + 2][laRow] = av.z;
        As[laCol + 3][laRow] = av.w;

        *(float4*)&Bs[lbRow][lbCol] = *(const float4*)&B[(k0 + lbRow) * 128 + lbCol];
        __syncthreads();

#pragma unroll
        for (int k = 0; k < 8; k++) {
            float4 a0 = *(const float4*)&As[k][tr * 8];
            float4 a1 = *(const float4*)&As[k][tr * 8 + 4];
            ulonglong2 rb0 = *(const ulonglong2*)&Bs[k][tc * 8];
            ulonglong2 rb1 = *(const ulonglong2*)&Bs[k][tc * 8 + 4];
            float avv[8] = {a0.x, a0.y, a0.z, a0.w, a1.x, a1.y, a1.z, a1.w};
#pragma unroll
            for (int i = 0; i < 8; i++) {
                unsigned long long ra;
                PACK2(ra, avv[i]);
                FMA2(acc[i][0], ra, rb0.x, acc[i][0]);
                FMA2(acc[i][1], ra, rb0.y, acc[i][1]);
                FMA2(acc[i][2], ra, rb1.x, acc[i][2]);
                FMA2(acc[i][3], ra, rb1.y, acc[i][3]);
            }
        }
        __syncthreads();
    }

    float4 as0 = *(const float4*)&a_src[tc * 8];
    float4 as1 = *(const float4*)&a_src[tc * 8 + 4];
    float4 ad0 = *(const float4*)&a_dst[tc * 8];
    float4 ad1 = *(const float4*)&a_dst[tc * 8 + 4];

#pragma unroll
    for (int i = 0; i < 8; i++) {
        float c0, c1, c2, c3, c4, c5, c6, c7;
        UNPACK2(c0, c1, acc[i][0]);
        UNPACK2(c2, c3, acc[i][1]);
        UNPACK2(c4, c5, acc[i][2]);
        UNPACK2(c6, c7, acc[i][3]);

        int row = row0 + tr * 8 + i;
        if (row < M) {
            __half2 p01 = __floats2half2_rn(c0, c1);
            __half2 p23 = __floats2half2_rn(c2, c3);
            __half2 p45 = __floats2half2_rn(c4, c5);
            __half2 p67 = __floats2half2_rn(c6, c7);
            uint4 pk;
            pk.x = *(unsigned*)&p01; pk.y = *(unsigned*)&p23;
            pk.z = *(unsigned*)&p45; pk.w = *(unsigned*)&p67;
            *(uint4*)&C16[(size_t)row * 128 + tc * 8] = pk;
        }

        float ds = c0 * as0.x + c1 * as0.y + c2 * as0.z + c3 * as0.w
                 + c4 * as1.x + c5 * as1.y + c6 * as1.z + c7 * as1.w;
        float dd = c0 * ad0.x + c1 * ad0.y + c2 * ad0.z + c3 * ad0.w
                 + c4 * ad1.x + c5 * ad1.y + c6 * ad1.z + c7 * ad1.w;
#pragma unroll
        for (int o = 4; o > 0; o >>= 1) {
            ds += __shfl_down_sync(0xffffffffu, ds, o, 8);
            dd += __shfl_down_sync(0xffffffffu, dd, o, 8);
        }
        if (row < M && (tc & 7) == 0) {
            int head = tc >> 3;
            g_esrc[row * 2 + head] = ds;
            g_edst[row * 2 + head] = dd;
        }
    }
}

// ---------------- edge aggregation: one warp per dst, fp16 gather ----------
__global__ __launch_bounds__(256) void k_agg(const float* __restrict__ bias,
                                             float* __restrict__ out, int do_relu) {
    int warp = (blockIdx.x * blockDim.x + threadIdx.x) >> 5;
    int lane = threadIdx.x & 31;
    if (warp >= N_NODES) return;

    const int d    = warp;
    const int head = lane >> 4;
    const float ed = g_edst[d * 2 + head];
    const int beg  = g_rowptr[d];
    const int end  = g_rowptr[d + 1];

    const uint2* __restrict__ h2 = (const uint2*)g_h16;   // 32 × uint2 per node

    float m = -1e30f, s = 0.f;
    float4 acc = make_float4(0.f, 0.f, 0.f, 0.f);

    int e = beg;
    for (; e + 1 < end; e += 2) {
        int c0 = g_col[e];
        int c1 = g_col[e + 1];
        float es0 = g_esrc[c0 * 2 + head];
        float es1 = g_esrc[c1 * 2 + head];
        uint2 r0 = h2[(size_t)c0 * 32 + lane];
        uint2 r1 = h2[(size_t)c1 * 32 + lane];

        float x0 = es0 + ed;
        float x1 = es1 + ed;
        float lv0 = x0 > 0.f ? x0 : NEG_SLOPE * x0;
        float lv1 = x1 > 0.f ? x1 : NEG_SLOPE * x1;
        float nm = fmaxf(m, fmaxf(lv0, lv1));
        float sc = __expf(m - nm);
        float p0 = __expf(lv0 - nm);
        float p1 = __expf(lv1 - nm);

        float2 f0a = __half22float2(*(__half2*)&r0.x);
        float2 f0b = __half22float2(*(__half2*)&r0.y);
        float2 f1a = __half22float2(*(__half2*)&r1.x);
        float2 f1b = __half22float2(*(__half2*)&r1.y);

        s     = s * sc + p0 + p1;
        acc.x = acc.x * sc + p0 * f0a.x + p1 * f1a.x;
        acc.y = acc.y * sc + p0 * f0a.y + p1 * f1a.y;
        acc.z = acc.z * sc + p0 * f0b.x + p1 * f1b.x;
        acc.w = acc.w * sc + p0 * f0b.y + p1 * f1b.y;
        m = nm;
    }
    if (e < end) {
        int c0 = g_col[e];
        float es0 = g_esrc[c0 * 2 + head];
        uint2 r0 = h2[(size_t)c0 * 32 + lane];
        float x0 = es0 + ed;
        float lv0 = x0 > 0.f ? x0 : NEG_SLOPE * x0;
        float nm = fmaxf(m, lv0);
        float sc = __expf(m - nm);
        float p0 = __expf(lv0 - nm);
        float2 f0a = __half22float2(*(__half2*)&r0.x);
        float2 f0b = __half22float2(*(__half2*)&r0.y);
        s     = s * sc + p0;
        acc.x = acc.x * sc + p0 * f0a.x;
        acc.y = acc.y * sc + p0 * f0a.y;
        acc.z = acc.z * sc + p0 * f0b.x;
        acc.w = acc.w * sc + p0 * f0b.y;
        m = nm;
    }

    float inv = 1.f / (s + 1e-16f);
    float4 bv = ((const float4*)bias)[lane];
    float4 o;
    o.x = acc.x * inv + bv.x;
    o.y = acc.y * inv + bv.y;
    o.z = acc.z * inv + bv.z;
    o.w = acc.w * inv + bv.w;
    if (do_relu) {
        o.x = fmaxf(o.x, 0.f); o.y = fmaxf(o.y, 0.f);
        o.z = fmaxf(o.z, 0.f); o.w = fmaxf(o.w, 0.f);
    }
    ((float4*)out)[(size_t)d * 32 + lane] = o;
}

// ---------------- host side ----------------
static void run_layer(const float* xin, const float* W, const float* a_src,
                      const float* a_dst, const float* b, __half* h16,
                      float* out_buf, int do_relu) {
    const int gemm_blocks = (N_NODES + 127) / 128;
    k_sgemm_fused<<<gemm_blocks, 256>>>(xin, W, h16, a_src, a_dst, N_NODES);
    const int warp_blocks = (N_NODES * 32 + 255) / 256;
    k_agg<<<warp_blocks, 256>>>(b, out_buf, do_relu);
}

extern "C" void kernel_launch(void* const* d_in, const int* in_sizes, int n_in,
                              void* d_out, int out_size) {
    const float* x      = (const float*)d_in[0];
    const void*  ei     = d_in[1];
    const float* W_in   = (const float*)d_in[2];
    const float* as_in  = (const float*)d_in[3];
    const float* ad_in  = (const float*)d_in[4];
    const float* b_in   = (const float*)d_in[5];
    const float* W_h    = (const float*)d_in[6];
    const float* as_h   = (const float*)d_in[7];
    const float* ad_h   = (const float*)d_in[8];
    const float* b_h    = (const float*)d_in[9];
    const float* W_out  = (const float*)d_in[10];
    const float* as_out = (const float*)d_in[11];
    const float* ad_out = (const float*)d_in[12];
    const float* b_out  = (const float*)d_in[13];
    float* out = (float*)d_out;

    __half* p_h16 = nullptr;
    float*  p_x   = nullptr;
    cudaGetSymbolAddress((void**)&p_h16, g_h16);
    cudaGetSymbolAddress((void**)&p_x, g_x);

    // ---- CSR build (deterministic, recomputed each replay) ----
    const int eb = (N_EDGES + 255) / 256;
    const int nb = (N_NODES + 255) / 256;
    k_init_detect<<<nb, 256>>>((const long long*)ei);
    k_convert_hist<<<eb, 256>>>(ei);
    k_scan1<<<SCAN_NBLK, SCAN_BLK>>>();
    k_scan3_selfloop<<<SCAN_NBLK, SCAN_BLK>>>();
    k_scatter<<<eb, 256>>>();

    // ---- 4 GAT layers ----
    run_layer(x,   W_in,            as_in,      ad_in,      b_in,      p_h16, p_x, 1);
    run_layer(p_x, W_h,             as_h,       ad_h,       b_h,       p_h16, p_x, 1);
    run_layer(p_x, W_h + 128 * 128, as_h + 128, ad_h + 128, b_h + 128, p_h16, p_x, 1);
    run_layer(p_x, W_out,           as_out,     ad_out,     b_out,     p_h16, out, 0);
}

// round 7
// speedup vs baseline: 1.2167x; 1.0739x over previous
#include <cuda_runtime.h>
#include <cuda_fp16.h>

// Problem constants
#define N_NODES 50000
#define N_EDGES 1600000
#define E_TOT   (N_EDGES + N_NODES)
#define FDIM    128
#define NHEAD   2
#define NEG_SLOPE 0.2f

#define SCAN_BLK 1024
#define SCAN_NBLK ((N_NODES + SCAN_BLK - 1) / SCAN_BLK)   // 49

// ---------------- device scratch ----------------
__device__ int g_is64;
__device__ int g_src[N_EDGES];
__device__ int g_dst[N_EDGES];
__device__ int g_counts[N_NODES];
__device__ int g_rowptr[N_NODES + 1];
__device__ int g_fill[N_NODES];
__device__ int g_col[E_TOT];
__device__ int g_partials[64];
__device__ __align__(16) __half g_h16[(size_t)N_NODES * FDIM];   // fp16 features for gather
__device__ __align__(16) float  g_x[(size_t)N_NODES * FDIM];     // fp32 layer output
__device__ __align__(16) float  g_esrc[N_NODES * NHEAD];
__device__ __align__(16) float  g_edst[N_NODES * NHEAD];

// ---------------- packed f32x2 helpers ----------------
#define FMA2(d, a, b, c) \
    asm("fma.rn.f32x2 %0, %1, %2, %3;" : "=l"(d) : "l"(a), "l"(b), "l"(c))
#define PACK2(d, x) \
    asm("mov.b64 %0, {%1, %1};" : "=l"(d) : "r"(__float_as_uint(x)))
#define UNPACK2(lo, hi, v) \
    do { unsigned _l, _h; \
         asm("mov.b64 {%0, %1}, %2;" : "=r"(_l), "=r"(_h) : "l"(v)); \
         lo = __uint_as_float(_l); hi = __uint_as_float(_h); } while (0)

// ---------------- CSR build ----------------
__global__ void k_init_detect(const long long* ei) {
    int i = blockIdx.x * blockDim.x + threadIdx.x;
    if (i < N_NODES) g_counts[i] = 1;   // self loop
    if (i == 0) {
        int ok = 1;
        for (int t = 0; t < 16; t++) {
            long long v = ei[t];
            if (v < 0 || v >= (long long)N_NODES) { ok = 0; break; }
        }
        g_is64 = ok;
    }
}

__global__ void k_convert_hist(const void* eiv) {
    int e = blockIdx.x * blockDim.x + threadIdx.x;
    if (e >= N_EDGES) return;
    int s, d;
    if (g_is64) {
        const long long* p = (const long long*)eiv;
        s = (int)p[e];
        d = (int)p[N_EDGES + e];
    } else {
        const int* p = (const int*)eiv;
        s = p[e];
        d = p[N_EDGES + e];
    }
    g_src[e] = s;
    g_dst[e] = d;
    atomicAdd(&g_counts[d], 1);
}

__global__ void k_scan1() {
    __shared__ int sh[SCAN_BLK];
    int i = blockIdx.x * SCAN_BLK + threadIdx.x;
    int v = (i < N_NODES) ? g_counts[i] : 0;
    sh[threadIdx.x] = v;
    __syncthreads();
    for (int o = 1; o < SCAN_BLK; o <<= 1) {
        int t = 0;
        if ((int)threadIdx.x >= o) t = sh[threadIdx.x - o];
        __syncthreads();
        sh[threadIdx.x] += t;
        __syncthreads();
    }
    if (i < N_NODES) g_rowptr[i] = sh[threadIdx.x] - v;   // block-local exclusive
    if (threadIdx.x == SCAN_BLK - 1) g_partials[blockIdx.x] = sh[SCAN_BLK - 1];
}

// add block offsets (each block re-scans the 49 partials locally) + self loop
__global__ void k_scan3_selfloop() {
    __shared__ int sh[64];
    if (threadIdx.x < 64)
        sh[threadIdx.x] = ((int)threadIdx.x < SCAN_NBLK) ? g_partials[threadIdx.x] : 0;
    __syncthreads();
    for (int o = 1; o < 64; o <<= 1) {
        int t = 0;
        if (threadIdx.x < 64 && (int)threadIdx.x >= o) t = sh[threadIdx.x - o];
        __syncthreads();
        if (threadIdx.x < 64) sh[threadIdx.x] += t;
        __syncthreads();
    }
    int blockOff = (blockIdx.x == 0) ? 0 : sh[blockIdx.x - 1];  // exclusive
    int i = blockIdx.x * SCAN_BLK + threadIdx.x;
    if (i < N_NODES) {
        int rp = g_rowptr[i] + blockOff;
        g_rowptr[i] = rp;
        g_col[rp] = i;      // self loop in slot 0
        g_fill[i] = 1;
    }
    if (i == 0) g_rowptr[N_NODES] = E_TOT;
}

__global__ void k_scatter() {
    int e = blockIdx.x * blockDim.x + threadIdx.x;
    if (e >= N_EDGES) return;
    int d = g_dst[e];
    int pos = g_rowptr[d] + atomicAdd(&g_fill[d], 1);
    g_col[pos] = g_src[e];
}

// ---------------- SGEMM (f32x2) + fused logits, fp16 output ----------------
__global__ __launch_bounds__(256, 2) void k_sgemm_fused(
    const float* __restrict__ A, const float* __restrict__ B,
    __half* __restrict__ C16,
    const float* __restrict__ a_src, const float* __restrict__ a_dst, int M) {
    __shared__ float As[8][128];   // transposed: As[k][m]
    __shared__ float Bs[8][128];

    const int tid  = threadIdx.x;
    const int row0 = blockIdx.x * 128;
    const int tr   = tid >> 4;
    const int tc   = tid & 15;

    const int laRow = tid >> 1;
    const int laCol = (tid & 1) * 4;
    const int lbRow = tid >> 5;
    const int lbCol = (tid & 31) * 4;

    unsigned long long acc[8][4];
#pragma unroll
    for (int i = 0; i < 8; i++)
#pragma unroll
        for (int p = 0; p < 4; p++) acc[i][p] = 0ull;

    for (int k0 = 0; k0 < 128; k0 += 8) {
        float4 av = make_float4(0.f, 0.f, 0.f, 0.f);
        int arow = row0 + laRow;
        if (arow < M) av = *(const float4*)&A[(size_t)arow * 128 + k0 + laCol];
        As[laCol + 0][laRow] = av.x;
        As[laCol + 1][laRow] = av.y;
        As[laCol + 2][laRow] = av.z;
        As[laCol + 3][laRow] = av.w;

        *(float4*)&Bs[lbRow][lbCol] = *(const float4*)&B[(k0 + lbRow) * 128 + lbCol];
        __syncthreads();

#pragma unroll
        for (int k = 0; k < 8; k++) {
            float4 a0 = *(const float4*)&As[k][tr * 8];
            float4 a1 = *(const float4*)&As[k][tr * 8 + 4];
            ulonglong2 rb0 = *(const ulonglong2*)&Bs[k][tc * 8];
            ulonglong2 rb1 = *(const ulonglong2*)&Bs[k][tc * 8 + 4];
            float avv[8] = {a0.x, a0.y, a0.z, a0.w, a1.x, a1.y, a1.z, a1.w};
#pragma unroll
            for (int i = 0; i < 8; i++) {
                unsigned long long ra;
                PACK2(ra, avv[i]);
                FMA2(acc[i][0], ra, rb0.x, acc[i][0]);
                FMA2(acc[i][1], ra, rb0.y, acc[i][1]);
                FMA2(acc[i][2], ra, rb1.x, acc[i][2]);
                FMA2(acc[i][3], ra, rb1.y, acc[i][3]);
            }
        }
        __syncthreads();
    }

    float4 as0 = *(const float4*)&a_src[tc * 8];
    float4 as1 = *(const float4*)&a_src[tc * 8 + 4];
    float4 ad0 = *(const float4*)&a_dst[tc * 8];
    float4 ad1 = *(const float4*)&a_dst[tc * 8 + 4];

#pragma unroll
    for (int i = 0; i < 8; i++) {
        float c0, c1, c2, c3, c4, c5, c6, c7;
        UNPACK2(c0, c1, acc[i][0]);
        UNPACK2(c2, c3, acc[i][1]);
        UNPACK2(c4, c5, acc[i][2]);
        UNPACK2(c6, c7, acc[i][3]);

        int row = row0 + tr * 8 + i;
        if (row < M) {
            __half2 p01 = __floats2half2_rn(c0, c1);
            __half2 p23 = __floats2half2_rn(c2, c3);
            __half2 p45 = __floats2half2_rn(c4, c5);
            __half2 p67 = __floats2half2_rn(c6, c7);
            uint4 pk;
            pk.x = *(unsigned*)&p01; pk.y = *(unsigned*)&p23;
            pk.z = *(unsigned*)&p45; pk.w = *(unsigned*)&p67;
            *(uint4*)&C16[(size_t)row * 128 + tc * 8] = pk;
        }

        float ds = c0 * as0.x + c1 * as0.y + c2 * as0.z + c3 * as0.w
                 + c4 * as1.x + c5 * as1.y + c6 * as1.z + c7 * as1.w;
        float dd = c0 * ad0.x + c1 * ad0.y + c2 * ad0.z + c3 * ad0.w
                 + c4 * ad1.x + c5 * ad1.y + c6 * ad1.z + c7 * ad1.w;
#pragma unroll
        for (int o = 4; o > 0; o >>= 1) {
            ds += __shfl_down_sync(0xffffffffu, ds, o, 8);
            dd += __shfl_down_sync(0xffffffffu, dd, o, 8);
        }
        if (row < M && (tc & 7) == 0) {
            int head = tc >> 3;
            g_esrc[row * 2 + head] = ds;
            g_edst[row * 2 + head] = dd;
        }
    }
}

// ---------------- edge aggregation: one warp per dst ------------------------
// No online max (logits provably bounded << 80): s and acc are plain FMA
// accumulations, so all loads can be batched 4-wide for MLP.
__global__ __launch_bounds__(256) void k_agg(const float* __restrict__ bias,
                                             float* __restrict__ out, int do_relu) {
    int warp = (blockIdx.x * blockDim.x + threadIdx.x) >> 5;
    int lane = threadIdx.x & 31;
    if (warp >= N_NODES) return;

    const int d    = warp;
    const int head = lane >> 4;
    const float ed = __ldg(&g_edst[d * 2 + head]);
    const int beg  = __ldg(&g_rowptr[d]);
    const int end  = __ldg(&g_rowptr[d + 1]);

    const uint2* __restrict__ h2 = (const uint2*)g_h16;
    const int* __restrict__ col = g_col;
    const float* __restrict__ esrc = g_esrc;

    float s = 0.f;
    float4 acc = make_float4(0.f, 0.f, 0.f, 0.f);

    int e = beg;
#pragma unroll 1
    for (; e + 4 <= end; e += 4) {
        int c0 = __ldg(&col[e]);
        int c1 = __ldg(&col[e + 1]);
        int c2 = __ldg(&col[e + 2]);
        int c3 = __ldg(&col[e + 3]);

        float es0 = __ldg(&esrc[c0 * 2 + head]);
        float es1 = __ldg(&esrc[c1 * 2 + head]);
        float es2 = __ldg(&esrc[c2 * 2 + head]);
        float es3 = __ldg(&esrc[c3 * 2 + head]);
        uint2 r0 = __ldg(&h2[(size_t)c0 * 32 + lane]);
        uint2 r1 = __ldg(&h2[(size_t)c1 * 32 + lane]);
        uint2 r2 = __ldg(&h2[(size_t)c2 * 32 + lane]);
        uint2 r3 = __ldg(&h2[(size_t)c3 * 32 + lane]);

        float x0 = es0 + ed, x1 = es1 + ed, x2 = es2 + ed, x3 = es3 + ed;
        float lv0 = fminf(x0 > 0.f ? x0 : NEG_SLOPE * x0, 80.f);
        float lv1 = fminf(x1 > 0.f ? x1 : NEG_SLOPE * x1, 80.f);
        float lv2 = fminf(x2 > 0.f ? x2 : NEG_SLOPE * x2, 80.f);
        float lv3 = fminf(x3 > 0.f ? x3 : NEG_SLOPE * x3, 80.f);
        float p0 = __expf(lv0);
        float p1 = __expf(lv1);
        float p2 = __expf(lv2);
        float p3 = __expf(lv3);

        float2 f0a = __half22float2(*(__half2*)&r0.x);
        float2 f0b = __half22float2(*(__half2*)&r0.y);
        float2 f1a = __half22float2(*(__half2*)&r1.x);
        float2 f1b = __half22float2(*(__half2*)&r1.y);
        float2 f2a = __half22float2(*(__half2*)&r2.x);
        float2 f2b = __half22float2(*(__half2*)&r2.y);
        float2 f3a = __half22float2(*(__half2*)&r3.x);
        float2 f3b = __half22float2(*(__half2*)&r3.y);

        s += (p0 + p1) + (p2 + p3);
        acc.x += p0 * f0a.x + p1 * f1a.x + p2 * f2a.x + p3 * f3a.x;
        acc.y += p0 * f0a.y + p1 * f1a.y + p2 * f2a.y + p3 * f3a.y;
        acc.z += p0 * f0b.x + p1 * f1b.x + p2 * f2b.x + p3 * f3b.x;
        acc.w += p0 * f0b.y + p1 * f1b.y + p2 * f2b.y + p3 * f3b.y;
    }
#pragma unroll 1
    for (; e < end; e++) {
        int c0 = __ldg(&col[e]);
        float es0 = __ldg(&esrc[c0 * 2 + head]);
        uint2 r0 = __ldg(&h2[(size_t)c0 * 32 + lane]);
        float x0 = es0 + ed;
        float lv0 = fminf(x0 > 0.f ? x0 : NEG_SLOPE * x0, 80.f);
        float p0 = __expf(lv0);
        float2 f0a = __half22float2(*(__half2*)&r0.x);
        float2 f0b = __half22float2(*(__half2*)&r0.y);
        s += p0;
        acc.x += p0 * f0a.x;
        acc.y += p0 * f0a.y;
        acc.z += p0 * f0b.x;
        acc.w += p0 * f0b.y;
    }

    float inv = 1.f / (s + 1e-16f);
    float4 bv = __ldg(&((const float4*)bias)[lane]);
    float4 o;
    o.x = acc.x * inv + bv.x;
    o.y = acc.y * inv + bv.y;
    o.z = acc.z * inv + bv.z;
    o.w = acc.w * inv + bv.w;
    if (do_relu) {
        o.x = fmaxf(o.x, 0.f); o.y = fmaxf(o.y, 0.f);
        o.z = fmaxf(o.z, 0.f); o.w = fmaxf(o.w, 0.f);
    }
    ((float4*)out)[(size_t)d * 32 + lane] = o;
}

// ---------------- host side ----------------
static void run_layer(const float* xin, const float* W, const float* a_src,
                      const float* a_dst, const float* b, __half* h16,
                      float* out_buf, int do_relu) {
    const int gemm_blocks = (N_NODES + 127) / 128;
    k_sgemm_fused<<<gemm_blocks, 256>>>(xin, W, h16, a_src, a_dst, N_NODES);
    const int warp_blocks = (N_NODES * 32 + 255) / 256;
    k_agg<<<warp_blocks, 256>>>(b, out_buf, do_relu);
}

extern "C" void kernel_launch(void* const* d_in, const int* in_sizes, int n_in,
                              void* d_out, int out_size) {
    const float* x      = (const float*)d_in[0];
    const void*  ei     = d_in[1];
    const float* W_in   = (const float*)d_in[2];
    const float* as_in  = (const float*)d_in[3];
    const float* ad_in  = (const float*)d_in[4];
    const float* b_in   = (const float*)d_in[5];
    const float* W_h    = (const float*)d_in[6];
    const float* as_h   = (const float*)d_in[7];
    const float* ad_h   = (const float*)d_in[8];
    const float* b_h    = (const float*)d_in[9];
    const float* W_out  = (const float*)d_in[10];
    const float* as_out = (const float*)d_in[11];
    const float* ad_out = (const float*)d_in[12];
    const float* b_out  = (const float*)d_in[13];
    float* out = (float*)d_out;

    __half* p_h16 = nullptr;
    float*  p_x   = nullptr;
    cudaGetSymbolAddress((void**)&p_h16, g_h16);
    cudaGetSymbolAddress((void**)&p_x, g_x);

    // ---- CSR build (deterministic, recomputed each replay) ----
    const int eb = (N_EDGES + 255) / 256;
    const int nb = (N_NODES + 255) / 256;
    k_init_detect<<<nb, 256>>>((const long long*)ei);
    k_convert_hist<<<eb, 256>>>(ei);
    k_scan1<<<SCAN_NBLK, SCAN_BLK>>>();
    k_scan3_selfloop<<<SCAN_NBLK, SCAN_BLK>>>();
    k_scatter<<<eb, 256>>>();

    // ---- 4 GAT layers ----
    run_layer(x,   W_in,            as_in,      ad_in,      b_in,      p_h16, p_x, 1);
    run_layer(p_x, W_h,             as_h,       ad_h,       b_h,       p_h16, p_x, 1);
    run_layer(p_x, W_h + 128 * 128, as_h + 128, ad_h + 128, b_h + 128, p_h16, p_x, 1);
    run_layer(p_x, W_out,           as_out,     ad_out,     b_out,     p_h16, out, 0);
}

// round 8
// speedup vs baseline: 1.2982x; 1.0669x over previous
#include <cuda_runtime.h>
#include <cuda_fp16.h>

// Problem constants
#define N_NODES 50000
#define N_EDGES 1600000
#define E_TOT   (N_EDGES + N_NODES)
#define FDIM    128
#define NHEAD   2
#define NEG_SLOPE 0.2f

#define SCAN_BLK 1024
#define SCAN_NBLK ((N_NODES + SCAN_BLK - 1) / SCAN_BLK)   // 49

// ---------------- device scratch ----------------
__device__ int g_is64;
__device__ int g_src[N_EDGES];
__device__ int g_dst[N_EDGES];
__device__ int g_counts[N_NODES];
__device__ int g_rowptr[N_NODES + 1];
__device__ int g_fill[N_NODES];
__device__ __align__(16) int g_col[E_TOT];
__device__ int g_partials[64];
__device__ __align__(16) __half g_h16[(size_t)N_NODES * FDIM];   // fp16 features for gather
__device__ __align__(16) float  g_x[(size_t)N_NODES * FDIM];     // fp32 layer output
__device__ __align__(16) float  g_esrc[N_NODES * NHEAD];
__device__ __align__(16) float  g_edst[N_NODES * NHEAD];

// ---------------- packed f32x2 helpers ----------------
#define FMA2(d, a, b, c) \
    asm("fma.rn.f32x2 %0, %1, %2, %3;" : "=l"(d) : "l"(a), "l"(b), "l"(c))
#define PACK2(d, x) \
    asm("mov.b64 %0, {%1, %1};" : "=l"(d) : "r"(__float_as_uint(x)))
#define UNPACK2(lo, hi, v) \
    do { unsigned _l, _h; \
         asm("mov.b64 {%0, %1}, %2;" : "=r"(_l), "=r"(_h) : "l"(v)); \
         lo = __uint_as_float(_l); hi = __uint_as_float(_h); } while (0)

// ---------------- CSR build ----------------
__global__ void k_init_detect(const long long* ei) {
    int i = blockIdx.x * blockDim.x + threadIdx.x;
    if (i < N_NODES) g_counts[i] = 1;   // self loop
    if (i == 0) {
        int ok = 1;
        for (int t = 0; t < 16; t++) {
            long long v = ei[t];
            if (v < 0 || v >= (long long)N_NODES) { ok = 0; break; }
        }
        g_is64 = ok;
    }
}

__global__ void k_convert_hist(const void* eiv) {
    int e = blockIdx.x * blockDim.x + threadIdx.x;
    if (e >= N_EDGES) return;
    int s, d;
    if (g_is64) {
        const long long* p = (const long long*)eiv;
        s = (int)p[e];
        d = (int)p[N_EDGES + e];
    } else {
        const int* p = (const int*)eiv;
        s = p[e];
        d = p[N_EDGES + e];
    }
    g_src[e] = s;
    g_dst[e] = d;
    atomicAdd(&g_counts[d], 1);
}

__global__ void k_scan1() {
    __shared__ int sh[SCAN_BLK];
    int i = blockIdx.x * SCAN_BLK + threadIdx.x;
    int v = (i < N_NODES) ? g_counts[i] : 0;
    sh[threadIdx.x] = v;
    __syncthreads();
    for (int o = 1; o < SCAN_BLK; o <<= 1) {
        int t = 0;
        if ((int)threadIdx.x >= o) t = sh[threadIdx.x - o];
        __syncthreads();
        sh[threadIdx.x] += t;
        __syncthreads();
    }
    if (i < N_NODES) g_rowptr[i] = sh[threadIdx.x] - v;   // block-local exclusive
    if (threadIdx.x == SCAN_BLK - 1) g_partials[blockIdx.x] = sh[SCAN_BLK - 1];
}

// add block offsets (each block re-scans the 49 partials locally) + self loop
__global__ void k_scan3_selfloop() {
    __shared__ int sh[64];
    if (threadIdx.x < 64)
        sh[threadIdx.x] = ((int)threadIdx.x < SCAN_NBLK) ? g_partials[threadIdx.x] : 0;
    __syncthreads();
    for (int o = 1; o < 64; o <<= 1) {
        int t = 0;
        if (threadIdx.x < 64 && (int)threadIdx.x >= o) t = sh[threadIdx.x - o];
        __syncthreads();
        if (threadIdx.x < 64) sh[threadIdx.x] += t;
        __syncthreads();
    }
    int blockOff = (blockIdx.x == 0) ? 0 : sh[blockIdx.x - 1];  // exclusive
    int i = blockIdx.x * SCAN_BLK + threadIdx.x;
    if (i < N_NODES) {
        int rp = g_rowptr[i] + blockOff;
        g_rowptr[i] = rp;
        g_col[rp] = i;      // self loop in slot 0
        g_fill[i] = 1;
    }
    if (i == 0) g_rowptr[N_NODES] = E_TOT;
}

__global__ void k_scatter() {
    int e = blockIdx.x * blockDim.x + threadIdx.x;
    if (e >= N_EDGES) return;
    int d = g_dst[e];
    int pos = g_rowptr[d] + atomicAdd(&g_fill[d], 1);
    g_col[pos] = g_src[e];
}

// ---------------- SGEMM (f32x2) + fused logits, fp16 output ----------------
__global__ __launch_bounds__(256, 2) void k_sgemm_fused(
    const float* __restrict__ A, const float* __restrict__ B,
    __half* __restrict__ C16,
    const float* __restrict__ a_src, const float* __restrict__ a_dst, int M) {
    __shared__ float As[8][128];   // transposed: As[k][m]
    __shared__ float Bs[8][128];

    const int tid  = threadIdx.x;
    const int row0 = blockIdx.x * 128;
    const int tr   = tid >> 4;
    const int tc   = tid & 15;

    const int laRow = tid >> 1;
    const int laCol = (tid & 1) * 4;
    const int lbRow = tid >> 5;
    const int lbCol = (tid & 31) * 4;

    unsigned long long acc[8][4];
#pragma unroll
    for (int i = 0; i < 8; i++)
#pragma unroll
        for (int p = 0; p < 4; p++) acc[i][p] = 0ull;

    for (int k0 = 0; k0 < 128; k0 += 8) {
        float4 av = make_float4(0.f, 0.f, 0.f, 0.f);
        int arow = row0 + laRow;
        if (arow < M) av = *(const float4*)&A[(size_t)arow * 128 + k0 + laCol];
        As[laCol + 0][laRow] = av.x;
        As[laCol + 1][laRow] = av.y;
        As[laCol + 2][laRow] = av.z;
        As[laCol + 3][laRow] = av.w;

        *(float4*)&Bs[lbRow][lbCol] = *(const float4*)&B[(k0 + lbRow) * 128 + lbCol];
        __syncthreads();

#pragma unroll
        for (int k = 0; k < 8; k++) {
            float4 a0 = *(const float4*)&As[k][tr * 8];
            float4 a1 = *(const float4*)&As[k][tr * 8 + 4];
            ulonglong2 rb0 = *(const ulonglong2*)&Bs[k][tc * 8];
            ulonglong2 rb1 = *(const ulonglong2*)&Bs[k][tc * 8 + 4];
            float avv[8] = {a0.x, a0.y, a0.z, a0.w, a1.x, a1.y, a1.z, a1.w};
#pragma unroll
            for (int i = 0; i < 8; i++) {
                unsigned long long ra;
                PACK2(ra, avv[i]);
                FMA2(acc[i][0], ra, rb0.x, acc[i][0]);
                FMA2(acc[i][1], ra, rb0.y, acc[i][1]);
                FMA2(acc[i][2], ra, rb1.x, acc[i][2]);
                FMA2(acc[i][3], ra, rb1.y, acc[i][3]);
            }
        }
        __syncthreads();
    }

    float4 as0 = *(const float4*)&a_src[tc * 8];
    float4 as1 = *(const float4*)&a_src[tc * 8 + 4];
    float4 ad0 = *(const float4*)&a_dst[tc * 8];
    float4 ad1 = *(const float4*)&a_dst[tc * 8 + 4];

#pragma unroll
    for (int i = 0; i < 8; i++) {
        float c0, c1, c2, c3, c4, c5, c6, c7;
        UNPACK2(c0, c1, acc[i][0]);
        UNPACK2(c2, c3, acc[i][1]);
        UNPACK2(c4, c5, acc[i][2]);
        UNPACK2(c6, c7, acc[i][3]);

        int row = row0 + tr * 8 + i;
        if (row < M) {
            __half2 p01 = __floats2half2_rn(c0, c1);
            __half2 p23 = __floats2half2_rn(c2, c3);
            __half2 p45 = __floats2half2_rn(c4, c5);
            __half2 p67 = __floats2half2_rn(c6, c7);
            uint4 pk;
            pk.x = *(unsigned*)&p01; pk.y = *(unsigned*)&p23;
            pk.z = *(unsigned*)&p45; pk.w = *(unsigned*)&p67;
            *(uint4*)&C16[(size_t)row * 128 + tc * 8] = pk;
        }

        float ds = c0 * as0.x + c1 * as0.y + c2 * as0.z + c3 * as0.w
                 + c4 * as1.x + c5 * as1.y + c6 * as1.z + c7 * as1.w;
        float dd = c0 * ad0.x + c1 * ad0.y + c2 * ad0.z + c3 * ad0.w
                 + c4 * ad1.x + c5 * ad1.y + c6 * ad1.z + c7 * ad1.w;
#pragma unroll
        for (int o = 4; o > 0; o >>= 1) {
            ds += __shfl_down_sync(0xffffffffu, ds, o, 8);
            dd += __shfl_down_sync(0xffffffffu, dd, o, 8);
        }
        if (row < M && (tc & 7) == 0) {
            int head = tc >> 3;
            g_esrc[row * 2 + head] = ds;
            g_edst[row * 2 + head] = dd;
        }
    }
}

// ---------------- edge aggregation: one warp per dst ------------------------
// 8-wide batches; cols fetched as 2 uniform int4; exp computed on ONE lane
// per (edge, head) and broadcast with width-16 shfl (head-0 lanes pull from
// lanes 0..7, head-1 from 16..23). Plain sums (no online max; logits bounded,
// clamped at 80).
__global__ __launch_bounds__(256) void k_agg(const float* __restrict__ bias,
                                             float* __restrict__ out, int do_relu) {
    int warp = (blockIdx.x * blockDim.x + threadIdx.x) >> 5;
    int lane = threadIdx.x & 31;
    if (warp >= N_NODES) return;

    const int d    = warp;
    const int head = lane >> 4;
    const float ed = __ldg(&g_edst[d * 2 + head]);
    const int beg  = __ldg(&g_rowptr[d]);
    const int end  = __ldg(&g_rowptr[d + 1]);

    const uint2* __restrict__ h2 = (const uint2*)g_h16;
    const int* __restrict__ col = g_col;
    const float* __restrict__ esrc = g_esrc;

    float s = 0.f;
    float4 acc = make_float4(0.f, 0.f, 0.f, 0.f);

    int e = beg;
    // peel to 4-alignment (and handle short rows)
#pragma unroll 1
    for (; e < end && ((e & 3) || (end - e < 8)); e++) {
        int c0 = __ldg(&col[e]);
        float es0 = __ldg(&esrc[c0 * 2 + head]);
        uint2 r0 = __ldg(&h2[(size_t)c0 * 32 + lane]);
        float x0 = es0 + ed;
        float lv0 = fminf(x0 > 0.f ? x0 : NEG_SLOPE * x0, 80.f);
        float p0 = __expf(lv0);
        float2 f0a = __half22float2(*(__half2*)&r0.x);
        float2 f0b = __half22float2(*(__half2*)&r0.y);
        s += p0;
        acc.x += p0 * f0a.x;
        acc.y += p0 * f0a.y;
        acc.z += p0 * f0b.x;
        acc.w += p0 * f0b.y;
    }

    // 8-wide main loop
#pragma unroll 1
    for (; e + 8 <= end; e += 8) {
        int4 ca = __ldg((const int4*)&col[e]);
        int4 cb = __ldg((const int4*)&col[e + 4]);
        int cs[8] = {ca.x, ca.y, ca.z, ca.w, cb.x, cb.y, cb.z, cb.w};

        // my edge within the batch: lane&7 (dup across lane groups; 1 LDG)
        int myc = cs[lane & 7];
        float es = __ldg(&esrc[myc * 2 + head]);

        uint2 r[8];
#pragma unroll
        for (int j = 0; j < 8; j++)
            r[j] = __ldg(&h2[(size_t)cs[j] * 32 + lane]);

        float x  = es + ed;
        float lv = fminf(x > 0.f ? x : NEG_SLOPE * x, 80.f);
        float myp = __expf(lv);

#pragma unroll
        for (int j = 0; j < 8; j++) {
            float pj = __shfl_sync(0xffffffffu, myp, j, 16);
            float2 fa = __half22float2(*(__half2*)&r[j].x);
            float2 fb = __half22float2(*(__half2*)&r[j].y);
            s += pj;
            acc.x += pj * fa.x;
            acc.y += pj * fa.y;
            acc.z += pj * fb.x;
            acc.w += pj * fb.y;
        }
    }

    // tail
#pragma unroll 1
    for (; e < end; e++) {
        int c0 = __ldg(&col[e]);
        float es0 = __ldg(&esrc[c0 * 2 + head]);
        uint2 r0 = __ldg(&h2[(size_t)c0 * 32 + lane]);
        float x0 = es0 + ed;
        float lv0 = fminf(x0 > 0.f ? x0 : NEG_SLOPE * x0, 80.f);
        float p0 = __expf(lv0);
        float2 f0a = __half22float2(*(__half2*)&r0.x);
        float2 f0b = __half22float2(*(__half2*)&r0.y);
        s += p0;
        acc.x += p0 * f0a.x;
        acc.y += p0 * f0a.y;
        acc.z += p0 * f0b.x;
        acc.w += p0 * f0b.y;
    }

    float inv = 1.f / (s + 1e-16f);
    float4 bv = __ldg(&((const float4*)bias)[lane]);
    float4 o;
    o.x = acc.x * inv + bv.x;
    o.y = acc.y * inv + bv.y;
    o.z = acc.z * inv + bv.z;
    o.w = acc.w * inv + bv.w;
    if (do_relu) {
        o.x = fmaxf(o.x, 0.f); o.y = fmaxf(o.y, 0.f);
        o.z = fmaxf(o.z, 0.f); o.w = fmaxf(o.w, 0.f);
    }
    ((float4*)out)[(size_t)d * 32 + lane] = o;
}

// ---------------- host side ----------------
static void run_layer(const float* xin, const float* W, const float* a_src,
                      const float* a_dst, const float* b, __half* h16,
                      float* out_buf, int do_relu) {
    const int gemm_blocks = (N_NODES + 127) / 128;
    k_sgemm_fused<<<gemm_blocks, 256>>>(xin, W, h16, a_src, a_dst, N_NODES);
    const int warp_blocks = (N_NODES * 32 + 255) / 256;
    k_agg<<<warp_blocks, 256>>>(b, out_buf, do_relu);
}

extern "C" void kernel_launch(void* const* d_in, const int* in_sizes, int n_in,
                              void* d_out, int out_size) {
    const float* x      = (const float*)d_in[0];
    const void*  ei     = d_in[1];
    const float* W_in   = (const float*)d_in[2];
    const float* as_in  = (const float*)d_in[3];
    const float* ad_in  = (const float*)d_in[4];
    const float* b_in   = (const float*)d_in[5];
    const float* W_h    = (const float*)d_in[6];
    const float* as_h   = (const float*)d_in[7];
    const float* ad_h   = (const float*)d_in[8];
    const float* b_h    = (const float*)d_in[9];
    const float* W_out  = (const float*)d_in[10];
    const float* as_out = (const float*)d_in[11];
    const float* ad_out = (const float*)d_in[12];
    const float* b_out  = (const float*)d_in[13];
    float* out = (float*)d_out;

    __half* p_h16 = nullptr;
    float*  p_x   = nullptr;
    cudaGetSymbolAddress((void**)&p_h16, g_h16);
    cudaGetSymbolAddress((void**)&p_x, g_x);

    // ---- CSR build (deterministic, recomputed each replay) ----
    const int eb = (N_EDGES + 255) / 256;
    const int nb = (N_NODES + 255) / 256;
    k_init_detect<<<nb, 256>>>((const long long*)ei);
    k_convert_hist<<<eb, 256>>>(ei);
    k_scan1<<<SCAN_NBLK, SCAN_BLK>>>();
    k_scan3_selfloop<<<SCAN_NBLK, SCAN_BLK>>>();
    k_scatter<<<eb, 256>>>();

    // ---- 4 GAT layers ----
    run_layer(x,   W_in,            as_in,      ad_in,      b_in,      p_h16, p_x, 1);
    run_layer(p_x, W_h,             as_h,       ad_h,       b_h,       p_h16, p_x, 1);
    run_layer(p_x, W_h + 128 * 128, as_h + 128, ad_h + 128, b_h + 128, p_h16, p_x, 1);
    run_layer(p_x, W_out,           as_out,     ad_out,     b_out,     p_h16, out, 0);
}